// round 16
// baseline (speedup 1.0000x reference)
#include <cuda_runtime.h>
#include <cuda_fp16.h>
#include <math.h>
#include <stdint.h>

typedef unsigned long long ull;

#define NJ 52
#define NV 6890
#define NB 10
#define NP 459            // (NJ-1)*9
#define BATCH 512
#define R3 20670          // NV*3
#define NVP 6912          // padded NV
#define KC 496            // naked GEMM K: 459 pose | pad | 11 hi | pad | 11 lo | pad
#define NKS (KC/16)       // 31 k-steps
#define MROWS 20736       // 162*128 padded rows
#define HI0 464
#define HI1 475
#define LO0 480
#define LO1 491
#define KW 64             // skin GEMM K (52 joints padded)
#define JS 8              // jreg split factor
#define JCHUNK 862        // ceil(NV/8)
#define STG3 12288        // mma pipeline stage bytes (A 6144 + B 6144)

__constant__ int c_parents[NJ] = {
    -1,0,0,0,1,2,3,4,5,6,7,8,9,9,9,12,13,14,16,17,18,19,20,22,23,20,25,26,
    20,28,29,20,31,32,20,34,35,21,37,38,21,40,41,21,43,44,21,46,47,21,49,50};

// ---- scratch (__device__ globals: allocation-free) ----
__device__ __align__(16) __half d_Rf [(size_t)MROWS * KC];  // dirs fp16 (~20MB)
__device__ __align__(16) __half d_PH [(size_t)BATCH * KC];  // batch rows fp16
__device__ __align__(16) __half d_Wf [(size_t)NVP * KW];    // weights fp16
__device__ __align__(16) __half d_BA2[(size_t)BATCH * 16 * KW]; // A2 as MMA B operand
__device__ float d_Jp [NJ * JS * 33];    // jreg partials

// ---------------- mma.sync / ldmatrix / cp.async helpers (plain sm_103) -----
__device__ __forceinline__ uint32_t smem_u32(const void* p) {
    uint32_t a;
    asm("{ .reg .u64 t; cvta.to.shared.u64 t, %1; cvt.u32.u64 %0, t; }" : "=r"(a) : "l"(p));
    return a;
}
__device__ __forceinline__ void ldsm4(uint32_t* r, uint32_t addr) {
    asm volatile("ldmatrix.sync.aligned.m8n8.x4.shared.b16 {%0,%1,%2,%3}, [%4];"
                 : "=r"(r[0]), "=r"(r[1]), "=r"(r[2]), "=r"(r[3]) : "r"(addr));
}
__device__ __forceinline__ void mma16816(float* d, const uint32_t* a, const uint32_t* b) {
    asm volatile("mma.sync.aligned.m16n8k16.row.col.f32.f16.f16.f32 "
                 "{%0,%1,%2,%3}, {%4,%5,%6,%7}, {%8,%9}, {%0,%1,%2,%3};"
                 : "+f"(d[0]), "+f"(d[1]), "+f"(d[2]), "+f"(d[3])
                 : "r"(a[0]), "r"(a[1]), "r"(a[2]), "r"(a[3]), "r"(b[0]), "r"(b[1]));
}
__device__ __forceinline__ void cpasync16(uint32_t dst, const void* src) {
    asm volatile("cp.async.cg.shared.global [%0], [%1], 16;" :: "r"(dst), "l"(src));
}
__device__ __forceinline__ void cpcommit() {
    asm volatile("cp.async.commit_group;" ::: "memory");
}
__device__ __forceinline__ void cpwait1() {
    asm volatile("cp.async.wait_group 1;" ::: "memory");
}
__device__ __forceinline__ void cpwait0() {
    asm volatile("cp.async.wait_group 0;" ::: "memory");
}

// ---------------------------------------------------------------------------
// convert R_cat -> fp16
// ---------------------------------------------------------------------------
__global__ void convertR_kernel(const float* __restrict__ pd,
                                const float* __restrict__ sd,
                                const float* __restrict__ vt) {
    int gid = blockIdx.x * 256 + threadIdx.x;   // MROWS*62 threads
    int r  = gid / 62;
    int k0 = (gid % 62) * 8;
    if (r >= MROWS) return;
    __align__(16) __half h[8];
#pragma unroll
    for (int t = 0; t < 8; t++) {
        int k = k0 + t;
        float x = 0.f;
        if (r < R3) {
            if (k < NP) {
                x = pd[(size_t)r * NP + k];
            } else if (k >= HI0 && k < HI1) {
                int i = k - HI0;
                x = (i < NB) ? sd[(size_t)r * NB + i] : vt[r];
            } else if (k >= LO0 && k < LO1) {
                int i = k - LO0;
                float v = (i < NB) ? sd[(size_t)r * NB + i] : vt[r];
                x = v - __half2float(__float2half(v));
            }
        }
        h[t] = __float2half(x);
    }
    size_t o = (size_t)r * KC + k0;
    *(uint4*)&d_Rf[o] = *(uint4*)h;
}

// ---------------------------------------------------------------------------
// convert weights (NV x NJ) -> fp16 [NVP x KW] k-major
// ---------------------------------------------------------------------------
__global__ void convertW_kernel(const float* __restrict__ wgt) {
    int gid = blockIdx.x * 256 + threadIdx.x;   // NVP*8 threads
    int v  = gid >> 3;
    int k0 = (gid & 7) * 8;
    if (v >= NVP) return;
    __align__(16) __half h[8];
#pragma unroll
    for (int t = 0; t < 8; t++) {
        int j = k0 + t;
        float x = (v < NV && j < NJ) ? wgt[(size_t)v * NJ + j] : 0.f;
        h[t] = __float2half(x);
    }
    *(uint4*)&d_Wf[(size_t)v * KW + k0] = *(uint4*)h;
}

// ---------------------------------------------------------------------------
// jreg partials: block (j, s) reduces v-range chunk -> d_Jp[(j*JS+s)*33 + o]
// ---------------------------------------------------------------------------
__global__ void jregP_kernel(const float* __restrict__ Jreg,
                             const float* __restrict__ vt,
                             const float* __restrict__ sd) {
    int j = blockIdx.x;
    int s = blockIdx.y;
    int v0 = s * JCHUNK;
    int v1 = v0 + JCHUNK; if (v1 > NV) v1 = NV;
    int tid = threadIdx.x;          // 256 threads
    float acc[33];
#pragma unroll
    for (int o = 0; o < 33; o++) acc[o] = 0.f;
    for (int v = v0 + tid; v < v1; v += 256) {
        float jr = Jreg[(size_t)j * NV + v];
#pragma unroll
        for (int k = 0; k < 3; k++) {
            acc[k] += jr * vt[v * 3 + k];
#pragma unroll
            for (int q = 0; q < NB; q++)
                acc[3 + k * NB + q] += jr * sd[(size_t)(v * 3 + k) * NB + q];
        }
    }
    __shared__ float red[256];
    for (int o = 0; o < 33; o++) {
        red[tid] = acc[o];
        __syncthreads();
        for (int st = 128; st > 0; st >>= 1) {
            if (tid < st) red[tid] += red[tid + st];
            __syncthreads();
        }
        if (tid == 0) d_Jp[(j * JS + s) * 33 + o] = red[0];
        __syncthreads();
    }
}

// ---------------------------------------------------------------------------
// per-batch (128 threads): rodrigues, P (fp16), th_j (from partials),
// kinematic chain, BA2 (fp16 B operand), th_jtr
// ---------------------------------------------------------------------------
__global__ __launch_bounds__(128) void pose_kernel(const float* __restrict__ pose,
                                                   const float* __restrict__ betas,
                                                   const float* __restrict__ trans,
                                                   float* __restrict__ out_jtr) {
    int b = blockIdx.x;
    int tid = threadIdx.x;          // 128 threads
    __shared__ float rot_s[NJ][9];
    __shared__ float j_s[NJ][3];
    __shared__ float A_s[NJ][12];
    __shared__ float bet_s[NB];

    if (tid < NB) bet_s[tid] = betas[b * NB + tid];
    if (tid < NJ) {
        float x = pose[b * NJ * 3 + tid * 3 + 0];
        float y = pose[b * NJ * 3 + tid * 3 + 1];
        float z = pose[b * NJ * 3 + tid * 3 + 2];
        float th = sqrtf(x * x + y * y + z * z + 1e-8f);
        float inv = 1.f / th;
        float kx = x * inv, ky = y * inv, kz = z * inv;
        float s = sinf(th), c = cosf(th), oc = 1.f - c;
        rot_s[tid][0] = c + oc * kx * kx;
        rot_s[tid][1] = -s * kz + oc * kx * ky;
        rot_s[tid][2] =  s * ky + oc * kx * kz;
        rot_s[tid][3] =  s * kz + oc * ky * kx;
        rot_s[tid][4] = c + oc * ky * ky;
        rot_s[tid][5] = -s * kx + oc * ky * kz;
        rot_s[tid][6] = -s * ky + oc * kz * kx;
        rot_s[tid][7] =  s * kx + oc * kz * ky;
        rot_s[tid][8] = c + oc * kz * kz;
    }
    __syncthreads();

    // th_j = sum_s Jp[vt] + (sum_s Jp[sd]) @ betas
    for (int idx = tid; idx < NJ * 3; idx += 128) {
        int j = idx / 3, k = idx % 3;
        const float* pj = &d_Jp[j * JS * 33];
        float v = 0.f;
#pragma unroll
        for (int s = 0; s < JS; s++) v += pj[s * 33 + k];
#pragma unroll
        for (int q = 0; q < NB; q++) {
            float c = 0.f;
#pragma unroll
            for (int s = 0; s < JS; s++) c += pj[s * 33 + 3 + k * NB + q];
            v += c * bet_s[q];
        }
        j_s[j][k] = v;
    }
    // P = [pose_map | 0 | betas,1 (hi) | 0 | betas,1 (lo) | 0] fp16
    for (int k = tid; k < KC; k += 128) {
        float x = 0.f;
        if (k < NP) {
            int j = k / 9 + 1, e = k % 9;
            float iv = (e == 0 || e == 4 || e == 8) ? 1.f : 0.f;
            x = rot_s[j][e] - iv;
        } else if (k >= HI0 && k < HI1) {
            int i = k - HI0;
            x = (i < NB) ? bet_s[i] : 1.f;
        } else if (k >= LO0 && k < LO1) {
            int i = k - LO0;
            x = (i < NB) ? bet_s[i] : 1.f;
        }
        d_PH[(size_t)b * KC + k] = __float2half(x);
    }
    // zero this batch's BA2 slice (16 rows x KW)
    for (int idx = tid; idx < 16 * KW / 8; idx += 128) {
        uint4 z = make_uint4(0, 0, 0, 0);
        *(uint4*)&d_BA2[(size_t)b * 16 * KW + idx * 8] = z;
    }
    __syncthreads();

    if (tid == 0) {
#pragma unroll
        for (int m = 0; m < 3; m++) {
#pragma unroll
            for (int n = 0; n < 3; n++) A_s[0][m * 4 + n] = rot_s[0][m * 3 + n];
            A_s[0][m * 4 + 3] = j_s[0][m];
        }
        for (int i = 1; i < NJ; i++) {
            int p = c_parents[i];
            float t0 = j_s[i][0] - j_s[p][0];
            float t1 = j_s[i][1] - j_s[p][1];
            float t2 = j_s[i][2] - j_s[p][2];
#pragma unroll
            for (int m = 0; m < 3; m++) {
                float r0 = A_s[p][m * 4 + 0], r1 = A_s[p][m * 4 + 1], r2 = A_s[p][m * 4 + 2];
#pragma unroll
                for (int n = 0; n < 3; n++)
                    A_s[i][m * 4 + n] = r0 * rot_s[i][0 * 3 + n] + r1 * rot_s[i][1 * 3 + n] + r2 * rot_s[i][2 * 3 + n];
                A_s[i][m * 4 + 3] = r0 * t0 + r1 * t1 + r2 * t2 + A_s[p][m * 4 + 3];
            }
        }
    }
    __syncthreads();

    // A2 -> BA2 fp16 B-operand: row (b*16 + m*4+n), col j
    for (int idx = tid; idx < NJ * 3; idx += 128) {
        int j = idx / 3, m = idx % 3;
        float r0 = A_s[j][m * 4 + 0], r1 = A_s[j][m * 4 + 1], r2 = A_s[j][m * 4 + 2];
        float t  = A_s[j][m * 4 + 3];
        float tmp = r0 * j_s[j][0] + r1 * j_s[j][1] + r2 * j_s[j][2];
        size_t base = (size_t)b * 16 * KW + (size_t)(m * 4) * KW + j;
        d_BA2[base + 0 * KW] = __float2half(r0);
        d_BA2[base + 1 * KW] = __float2half(r1);
        d_BA2[base + 2 * KW] = __float2half(r2);
        d_BA2[base + 3 * KW] = __float2half(t - tmp);
        out_jtr[(size_t)b * NJ * 3 + j * 3 + m] = t + trans[b * 3 + m];
    }
}

// ---------------------------------------------------------------------------
// naked GEMM via mma.sync fp16: block tile 128 x 128
// 3-stage cp.async pipeline, single __syncthreads per k-step.
// minBlocksPerMultiprocessor=3 -> <=85 regs -> 3 blocks/SM (occ 25% -> 37.5%)
// ---------------------------------------------------------------------------
__global__ __launch_bounds__(256, 3) void mma_naked_kernel(float* __restrict__ out_vposed,
                                                           float* __restrict__ out_naked) {
    __shared__ __align__(16) __half sPipe[3 * STG3 / 2];

    const int tid  = threadIdx.x;
    const int wid  = tid >> 5;
    const int lane = tid & 31;
    const int wm = wid & 1;
    const int wn = wid >> 1;
    const int r0 = blockIdx.x * 128;
    const int b0 = blockIdx.y * 128;
    const uint32_t base_u = smem_u32(sPipe);

    const int crow = tid >> 1;
    const int cch  = tid & 1;
    const uint32_t dstoff = (uint32_t)(crow * 48 + cch * 16);
    const __half* gP = d_PH + (size_t)(b0 + crow) * KC + cch * 8;
    const __half* gR = d_Rf + (size_t)(r0 + crow) * KC + cch * 8;

    const uint32_t offA = (uint32_t)((wm * 64 + (lane & 15)) * 48 + (lane >> 4) * 16);
    const uint32_t offB = (uint32_t)((wn * 32 + (lane & 7) + ((lane >> 4) & 1) * 8) * 48
                                     + ((lane >> 3) & 1) * 16) + 6144;

    float d[4][4][4];
#pragma unroll
    for (int i = 0; i < 4; i++)
#pragma unroll
        for (int j = 0; j < 4; j++)
#pragma unroll
            for (int k = 0; k < 4; k++) d[i][j][k] = 0.f;

#pragma unroll
    for (int s = 0; s < 2; s++) {
        uint32_t sb = base_u + s * STG3;
        cpasync16(sb + dstoff, gP + s * 16);
        cpasync16(sb + 6144 + dstoff, gR + s * 16);
        cpcommit();
    }

    uint32_t sOff = 0;
    for (int ks = 0; ks < NKS; ks++) {
        if (ks < NKS - 1) cpwait1(); else cpwait0();
        __syncthreads();

        if (ks + 2 < NKS) {
            uint32_t pOff = sOff + 2 * STG3; if (pOff >= 3 * STG3) pOff -= 3 * STG3;
            uint32_t sb = base_u + pOff;
            int koff = (ks + 2) * 16;
            cpasync16(sb + dstoff, gP + koff);
            cpasync16(sb + 6144 + dstoff, gR + koff);
            cpcommit();
        }

        uint32_t sb = base_u + sOff;
        uint32_t bb[2][4];
        ldsm4(bb[0], sb + offB);
        ldsm4(bb[1], sb + offB + 768);
#pragma unroll
        for (int mi = 0; mi < 4; mi++) {
            uint32_t a[4];
            ldsm4(a, sb + offA + mi * 768);
            mma16816(d[mi][0], a, bb[0]);
            mma16816(d[mi][1], a, bb[0] + 2);
            mma16816(d[mi][2], a, bb[1]);
            mma16816(d[mi][3], a, bb[1] + 2);
        }
        sOff += STG3; if (sOff == 3 * STG3) sOff = 0;
    }

    int mbase = b0 + wm * 64 + (lane >> 2);
    int nbase = r0 + wn * 32 + (lane & 3) * 2;
#pragma unroll
    for (int mi = 0; mi < 4; mi++) {
        int m = mbase + mi * 16;
#pragma unroll
        for (int t = 0; t < 4; t++) {
            int n = nbase + t * 8;
            if (n < R3) {
                size_t o1 = (size_t)m * R3 + n;
                size_t o2 = (size_t)(m + 8) * R3 + n;
                float2 v01 = make_float2(d[mi][t][0], d[mi][t][1]);
                float2 v23 = make_float2(d[mi][t][2], d[mi][t][3]);
                *(float2*)(out_vposed + o1) = v01;
                *(float2*)(out_naked  + o1) = v01;
                *(float2*)(out_vposed + o2) = v23;
                *(float2*)(out_naked  + o2) = v23;
            }
        }
    }
}

// ---------------------------------------------------------------------------
// skin via mma.sync fp16: T = W @ A2 fused with apply. (R15-proven, 3 blk/SM)
// ---------------------------------------------------------------------------
__global__ __launch_bounds__(256, 3) void skin_mma_kernel(const float* __restrict__ trans,
                                                          const float* __restrict__ naked_in,
                                                          float* __restrict__ out_verts) {
    __shared__ __align__(16) __half sA[128 * 72];   // weights tile
    __shared__ __align__(16) __half sB[128 * 72];   // BA2 tile
    __shared__ __align__(8)  float  sH[8 * 386];    // naked slice
    float* sOut = (float*)sA;                       // overlay after mainloop

    const int tid  = threadIdx.x;
    const int wid  = tid >> 5;
    const int lane = tid & 31;
    const int wm = wid & 1;
    const int wn = wid >> 1;
    const int v0 = blockIdx.x * 128;
    const int b0 = blockIdx.y * 8;
    const int c0 = blockIdx.y * 128;

    for (int i = tid; i < 1024; i += 256) {
        int row = i >> 3, ch = i & 7;
        *(uint4*)&sA[row * 72 + ch * 8] = *(const uint4*)&d_Wf[(size_t)(v0 + row) * KW + ch * 8];
        *(uint4*)&sB[row * 72 + ch * 8] = *(const uint4*)&d_BA2[(size_t)(c0 + row) * KW + ch * 8];
    }
    for (int idx = tid; idx < 1536; idx += 256) {
        int b = idx / 192, off = (idx % 192) * 2;
        int gcol = v0 * 3 + off;
        float2 val = make_float2(0.f, 0.f);
        if (gcol < R3)
            val = *(const float2*)(naked_in + (size_t)(b0 + b) * R3 + gcol);
        sH[b * 386 + off]     = val.x;
        sH[b * 386 + off + 1] = val.y;
    }
    __syncthreads();

    const uint32_t offA = (uint32_t)((wm * 64 + (lane & 15)) * 144 + (lane >> 4) * 16);
    const uint32_t offB = (uint32_t)((wn * 32 + (lane & 7) + ((lane >> 4) & 1) * 8) * 144
                                     + ((lane >> 3) & 1) * 16);
    uint32_t aB = smem_u32(sA) + offA;
    uint32_t bB = smem_u32(sB) + offB;

    float d[4][4][4];
#pragma unroll
    for (int i = 0; i < 4; i++)
#pragma unroll
        for (int j = 0; j < 4; j++)
#pragma unroll
            for (int k = 0; k < 4; k++) d[i][j][k] = 0.f;

#pragma unroll
    for (int ks = 0; ks < 4; ks++) {
        uint32_t ko = ks * 32;
        uint32_t bb[2][4];
        ldsm4(bb[0], bB + ko);
        ldsm4(bb[1], bB + ko + 2304);
#pragma unroll
        for (int mi = 0; mi < 4; mi++) {
            uint32_t a[4];
            ldsm4(a, aB + ko + mi * 2304);
            mma16816(d[mi][0], a, bb[0]);
            mma16816(d[mi][1], a, bb[0] + 2);
            mma16816(d[mi][2], a, bb[1]);
            mma16816(d[mi][3], a, bb[1] + 2);
        }
    }
    __syncthreads();

    const int q = lane & 3;
#pragma unroll
    for (int u = 0; u < 2; u++) {
        int bl = wn * 2 + u;
        int bg = b0 + bl;
        float tx = trans[bg * 3 + 0], ty = trans[bg * 3 + 1], tz = trans[bg * 3 + 2];
#pragma unroll
        for (int mi = 0; mi < 4; mi++) {
#pragma unroll
            for (int rh = 0; rh < 2; rh++) {
                int vl = wm * 64 + mi * 16 + (lane >> 2) + rh * 8;
                int v = v0 + vl;
                bool valid = (v < NV);
                const float* hp = &sH[bl * 386 + vl * 3];
                float s0, s1;
                if ((q & 1) == 0) { s0 = hp[0]; s1 = hp[1]; }
                else              { s0 = hp[2]; s1 = 1.f; }
                float pA = d[mi][2 * u][rh * 2 + 0] * s0 + d[mi][2 * u][rh * 2 + 1] * s1;
                float pB = d[mi][2 * u + 1][rh * 2 + 0] * s0 + d[mi][2 * u + 1][rh * 2 + 1] * s1;
                pA += __shfl_xor_sync(0xffffffffu, pA, 1);
                pB += __shfl_xor_sync(0xffffffffu, pB, 1);
                if (valid) {
                    if (q == 0) {
                        sOut[bl * 386 + vl * 3 + 0] = pA + tx;
                        sOut[bl * 386 + vl * 3 + 2] = pB + tz;
                    } else if (q == 2) {
                        sOut[bl * 386 + vl * 3 + 1] = pA + ty;
                    }
                }
            }
        }
    }
    __syncthreads();

    for (int idx = tid; idx < 1536; idx += 256) {
        int b = idx / 192, off = (idx % 192) * 2;
        int gcol = v0 * 3 + off;
        if (gcol < R3) {
            float2 val = make_float2(sOut[b * 386 + off], sOut[b * 386 + off + 1]);
            *(float2*)(out_verts + (size_t)(b0 + b) * R3 + gcol) = val;
        }
    }
}

// ---------------------------------------------------------------------------
extern "C" void kernel_launch(void* const* d_in, const int* in_sizes, int n_in,
                              void* d_out, int out_size) {
    (void)in_sizes; (void)n_in; (void)out_size;
    const float* pose  = (const float*)d_in[0];
    const float* betas = (const float*)d_in[1];
    const float* trans = (const float*)d_in[2];
    const float* vt    = (const float*)d_in[3];
    const float* sd    = (const float*)d_in[4];
    const float* pd    = (const float*)d_in[5];
    const float* Jreg  = (const float*)d_in[6];
    const float* wgt   = (const float*)d_in[7];

    float* out        = (float*)d_out;
    float* out_verts  = out;
    float* out_jtr    = out_verts + (size_t)BATCH * R3;
    float* out_vposed = out_jtr   + (size_t)BATCH * NJ * 3;
    float* out_naked  = out_vposed + (size_t)BATCH * R3;

    int convThreads = MROWS * 62;
    convertR_kernel<<<(convThreads + 255) / 256, 256>>>(pd, sd, vt);              // 0
    jregP_kernel<<<dim3(NJ, JS), 256>>>(Jreg, vt, sd);                            // 1
    pose_kernel<<<BATCH, 128>>>(pose, betas, trans, out_jtr);                     // 2
    mma_naked_kernel<<<dim3(162, 4), 256>>>(out_vposed, out_naked);               // 3 (profiled)
    convertW_kernel<<<(NVP * 8 + 255) / 256, 256>>>(wgt);                         // 4
    skin_mma_kernel<<<dim3(NVP / 128, BATCH / 8), 256>>>(trans, out_naked, out_verts); // 5
}

// round 17
// speedup vs baseline: 1.2138x; 1.2138x over previous
#include <cuda_runtime.h>
#include <cuda_fp16.h>
#include <math.h>
#include <stdint.h>

typedef unsigned long long ull;

#define NJ 52
#define NV 6890
#define NB 10
#define NP 459            // (NJ-1)*9
#define BATCH 512
#define R3 20670          // NV*3
#define NVP 6912          // padded NV
#define KC 496            // naked GEMM K: 459 pose | pad | 11 hi | pad | 11 lo | pad
#define NKS (KC/16)       // 31 k-steps
#define MROWS 20736       // 162*128 padded rows
#define HI0 464
#define HI1 475
#define LO0 480
#define LO1 491
#define KW 64             // skin GEMM K (52 joints padded)
#define JS 8              // jreg split factor
#define JCHUNK 862        // ceil(NV/8)
#define STG3 12288        // mma pipeline stage bytes (A 6144 + B 6144)

__constant__ int c_parents[NJ] = {
    -1,0,0,0,1,2,3,4,5,6,7,8,9,9,9,12,13,14,16,17,18,19,20,22,23,20,25,26,
    20,28,29,20,31,32,20,34,35,21,37,38,21,40,41,21,43,44,21,46,47,21,49,50};
// topological depth of each joint (max 10 -> 11 levels)
__constant__ int c_level[NJ] = {
    0,1,1,1,2,2,2,3,3,3,4,4,4,4,4,5,5,5,6,6,7,7,
    8,9,10, 8,9,10, 8,9,10, 8,9,10, 8,9,10,
    8,9,10, 8,9,10, 8,9,10, 8,9,10, 8,9,10};

// ---- scratch (__device__ globals: allocation-free) ----
__device__ __align__(16) __half d_Rf [(size_t)MROWS * KC];  // dirs fp16 (~20MB)
__device__ __align__(16) __half d_PH [(size_t)BATCH * KC];  // batch rows fp16
__device__ __align__(16) __half d_Wf [(size_t)NVP * KW];    // weights fp16
__device__ __align__(16) __half d_BA2[(size_t)BATCH * 16 * KW]; // A2 as MMA B operand
__device__ float d_Jp [NJ * JS * 33];    // jreg partials

// ---------------- mma.sync / ldmatrix / cp.async helpers (plain sm_103) -----
__device__ __forceinline__ uint32_t smem_u32(const void* p) {
    uint32_t a;
    asm("{ .reg .u64 t; cvta.to.shared.u64 t, %1; cvt.u32.u64 %0, t; }" : "=r"(a) : "l"(p));
    return a;
}
__device__ __forceinline__ void ldsm4(uint32_t* r, uint32_t addr) {
    asm volatile("ldmatrix.sync.aligned.m8n8.x4.shared.b16 {%0,%1,%2,%3}, [%4];"
                 : "=r"(r[0]), "=r"(r[1]), "=r"(r[2]), "=r"(r[3]) : "r"(addr));
}
__device__ __forceinline__ void mma16816(float* d, const uint32_t* a, const uint32_t* b) {
    asm volatile("mma.sync.aligned.m16n8k16.row.col.f32.f16.f16.f32 "
                 "{%0,%1,%2,%3}, {%4,%5,%6,%7}, {%8,%9}, {%0,%1,%2,%3};"
                 : "+f"(d[0]), "+f"(d[1]), "+f"(d[2]), "+f"(d[3])
                 : "r"(a[0]), "r"(a[1]), "r"(a[2]), "r"(a[3]), "r"(b[0]), "r"(b[1]));
}
__device__ __forceinline__ void cpasync16(uint32_t dst, const void* src) {
    asm volatile("cp.async.cg.shared.global [%0], [%1], 16;" :: "r"(dst), "l"(src));
}
__device__ __forceinline__ void cpcommit() {
    asm volatile("cp.async.commit_group;" ::: "memory");
}
__device__ __forceinline__ void cpwait1() {
    asm volatile("cp.async.wait_group 1;" ::: "memory");
}
__device__ __forceinline__ void cpwait0() {
    asm volatile("cp.async.wait_group 0;" ::: "memory");
}

// ---------------------------------------------------------------------------
// convert R_cat -> fp16
// ---------------------------------------------------------------------------
__global__ void convertR_kernel(const float* __restrict__ pd,
                                const float* __restrict__ sd,
                                const float* __restrict__ vt) {
    int gid = blockIdx.x * 256 + threadIdx.x;   // MROWS*62 threads
    int r  = gid / 62;
    int k0 = (gid % 62) * 8;
    if (r >= MROWS) return;
    __align__(16) __half h[8];
#pragma unroll
    for (int t = 0; t < 8; t++) {
        int k = k0 + t;
        float x = 0.f;
        if (r < R3) {
            if (k < NP) {
                x = pd[(size_t)r * NP + k];
            } else if (k >= HI0 && k < HI1) {
                int i = k - HI0;
                x = (i < NB) ? sd[(size_t)r * NB + i] : vt[r];
            } else if (k >= LO0 && k < LO1) {
                int i = k - LO0;
                float v = (i < NB) ? sd[(size_t)r * NB + i] : vt[r];
                x = v - __half2float(__float2half(v));
            }
        }
        h[t] = __float2half(x);
    }
    size_t o = (size_t)r * KC + k0;
    *(uint4*)&d_Rf[o] = *(uint4*)h;
}

// ---------------------------------------------------------------------------
// convert weights (NV x NJ) -> fp16 [NVP x KW] k-major
// ---------------------------------------------------------------------------
__global__ void convertW_kernel(const float* __restrict__ wgt) {
    int gid = blockIdx.x * 256 + threadIdx.x;   // NVP*8 threads
    int v  = gid >> 3;
    int k0 = (gid & 7) * 8;
    if (v >= NVP) return;
    __align__(16) __half h[8];
#pragma unroll
    for (int t = 0; t < 8; t++) {
        int j = k0 + t;
        float x = (v < NV && j < NJ) ? wgt[(size_t)v * NJ + j] : 0.f;
        h[t] = __float2half(x);
    }
    *(uint4*)&d_Wf[(size_t)v * KW + k0] = *(uint4*)h;
}

// ---------------------------------------------------------------------------
// jreg partials: block (j, s) reduces v-range chunk -> d_Jp[(j*JS+s)*33 + o]
// ---------------------------------------------------------------------------
__global__ void jregP_kernel(const float* __restrict__ Jreg,
                             const float* __restrict__ vt,
                             const float* __restrict__ sd) {
    int j = blockIdx.x;
    int s = blockIdx.y;
    int v0 = s * JCHUNK;
    int v1 = v0 + JCHUNK; if (v1 > NV) v1 = NV;
    int tid = threadIdx.x;          // 256 threads
    float acc[33];
#pragma unroll
    for (int o = 0; o < 33; o++) acc[o] = 0.f;
    for (int v = v0 + tid; v < v1; v += 256) {
        float jr = Jreg[(size_t)j * NV + v];
#pragma unroll
        for (int k = 0; k < 3; k++) {
            acc[k] += jr * vt[v * 3 + k];
#pragma unroll
            for (int q = 0; q < NB; q++)
                acc[3 + k * NB + q] += jr * sd[(size_t)(v * 3 + k) * NB + q];
        }
    }
    __shared__ float red[256];
    for (int o = 0; o < 33; o++) {
        red[tid] = acc[o];
        __syncthreads();
        for (int st = 128; st > 0; st >>= 1) {
            if (tid < st) red[tid] += red[tid + st];
            __syncthreads();
        }
        if (tid == 0) d_Jp[(j * JS + s) * 33 + o] = red[0];
        __syncthreads();
    }
}

// ---------------------------------------------------------------------------
// per-batch (128 threads): rodrigues, P (fp16), th_j (from partials),
// LEVEL-PARALLEL kinematic chain, BA2 (fp16 B operand), th_jtr
// ---------------------------------------------------------------------------
__global__ __launch_bounds__(128) void pose_kernel(const float* __restrict__ pose,
                                                   const float* __restrict__ betas,
                                                   const float* __restrict__ trans,
                                                   float* __restrict__ out_jtr) {
    int b = blockIdx.x;
    int tid = threadIdx.x;          // 128 threads
    __shared__ float rot_s[NJ][9];
    __shared__ float j_s[NJ][3];
    __shared__ float A_s[NJ][12];
    __shared__ float bet_s[NB];

    if (tid < NB) bet_s[tid] = betas[b * NB + tid];
    if (tid < NJ) {
        float x = pose[b * NJ * 3 + tid * 3 + 0];
        float y = pose[b * NJ * 3 + tid * 3 + 1];
        float z = pose[b * NJ * 3 + tid * 3 + 2];
        float th = sqrtf(x * x + y * y + z * z + 1e-8f);
        float inv = 1.f / th;
        float kx = x * inv, ky = y * inv, kz = z * inv;
        float s = sinf(th), c = cosf(th), oc = 1.f - c;
        rot_s[tid][0] = c + oc * kx * kx;
        rot_s[tid][1] = -s * kz + oc * kx * ky;
        rot_s[tid][2] =  s * ky + oc * kx * kz;
        rot_s[tid][3] =  s * kz + oc * ky * kx;
        rot_s[tid][4] = c + oc * ky * ky;
        rot_s[tid][5] = -s * kx + oc * ky * kz;
        rot_s[tid][6] = -s * ky + oc * kz * kx;
        rot_s[tid][7] =  s * kx + oc * kz * ky;
        rot_s[tid][8] = c + oc * kz * kz;
    }
    __syncthreads();

    // th_j = sum_s Jp[vt] + (sum_s Jp[sd]) @ betas
    for (int idx = tid; idx < NJ * 3; idx += 128) {
        int j = idx / 3, k = idx % 3;
        const float* pj = &d_Jp[j * JS * 33];
        float v = 0.f;
#pragma unroll
        for (int s = 0; s < JS; s++) v += pj[s * 33 + k];
#pragma unroll
        for (int q = 0; q < NB; q++) {
            float c = 0.f;
#pragma unroll
            for (int s = 0; s < JS; s++) c += pj[s * 33 + 3 + k * NB + q];
            v += c * bet_s[q];
        }
        j_s[j][k] = v;
    }
    // P = [pose_map | 0 | betas,1 (hi) | 0 | betas,1 (lo) | 0] fp16
    for (int k = tid; k < KC; k += 128) {
        float x = 0.f;
        if (k < NP) {
            int j = k / 9 + 1, e = k % 9;
            float iv = (e == 0 || e == 4 || e == 8) ? 1.f : 0.f;
            x = rot_s[j][e] - iv;
        } else if (k >= HI0 && k < HI1) {
            int i = k - HI0;
            x = (i < NB) ? bet_s[i] : 1.f;
        } else if (k >= LO0 && k < LO1) {
            int i = k - LO0;
            x = (i < NB) ? bet_s[i] : 1.f;
        }
        d_PH[(size_t)b * KC + k] = __float2half(x);
    }
    // zero this batch's BA2 slice (16 rows x KW)
    for (int idx = tid; idx < 16 * KW / 8; idx += 128) {
        uint4 z = make_uint4(0, 0, 0, 0);
        *(uint4*)&d_BA2[(size_t)b * 16 * KW + idx * 8] = z;
    }
    __syncthreads();

    // ---- level-parallel kinematic chain (depth 10 -> 11 level steps) ----
    // level 0: root rows
    for (int idx = tid; idx < 3; idx += 128) {
        int m = idx;
#pragma unroll
        for (int n = 0; n < 3; n++) A_s[0][m * 4 + n] = rot_s[0][m * 3 + n];
        A_s[0][m * 4 + 3] = j_s[0][m];
    }
    __syncthreads();
    for (int lev = 1; lev <= 10; lev++) {
        for (int idx = tid; idx < NJ * 3; idx += 128) {
            int j = idx / 3, m = idx % 3;
            if (c_level[j] == lev) {
                int p = c_parents[j];
                float t0 = j_s[j][0] - j_s[p][0];
                float t1 = j_s[j][1] - j_s[p][1];
                float t2 = j_s[j][2] - j_s[p][2];
                float r0 = A_s[p][m * 4 + 0], r1 = A_s[p][m * 4 + 1], r2 = A_s[p][m * 4 + 2];
#pragma unroll
                for (int n = 0; n < 3; n++)
                    A_s[j][m * 4 + n] = r0 * rot_s[j][0 * 3 + n] + r1 * rot_s[j][1 * 3 + n] + r2 * rot_s[j][2 * 3 + n];
                A_s[j][m * 4 + 3] = r0 * t0 + r1 * t1 + r2 * t2 + A_s[p][m * 4 + 3];
            }
        }
        __syncthreads();
    }

    // A2 -> BA2 fp16 B-operand: row (b*16 + m*4+n), col j
    for (int idx = tid; idx < NJ * 3; idx += 128) {
        int j = idx / 3, m = idx % 3;
        float r0 = A_s[j][m * 4 + 0], r1 = A_s[j][m * 4 + 1], r2 = A_s[j][m * 4 + 2];
        float t  = A_s[j][m * 4 + 3];
        float tmp = r0 * j_s[j][0] + r1 * j_s[j][1] + r2 * j_s[j][2];
        size_t base = (size_t)b * 16 * KW + (size_t)(m * 4) * KW + j;
        d_BA2[base + 0 * KW] = __float2half(r0);
        d_BA2[base + 1 * KW] = __float2half(r1);
        d_BA2[base + 2 * KW] = __float2half(r2);
        d_BA2[base + 3 * KW] = __float2half(t - tmp);
        out_jtr[(size_t)b * NJ * 3 + j * 3 + m] = t + trans[b * 3 + m];
    }
}

// ---------------------------------------------------------------------------
// naked GEMM via mma.sync fp16: block tile 128 x 128 (R12-proven: NO occ cap,
// regs 96 / 2 blocks/SM -- the (256,3) variant spills accumulators, 73->114us)
// 3-stage cp.async pipeline, single __syncthreads per k-step.
// ---------------------------------------------------------------------------
__global__ __launch_bounds__(256) void mma_naked_kernel(float* __restrict__ out_vposed,
                                                        float* __restrict__ out_naked) {
    __shared__ __align__(16) __half sPipe[3 * STG3 / 2];

    const int tid  = threadIdx.x;
    const int wid  = tid >> 5;
    const int lane = tid & 31;
    const int wm = wid & 1;
    const int wn = wid >> 1;
    const int r0 = blockIdx.x * 128;
    const int b0 = blockIdx.y * 128;
    const uint32_t base_u = smem_u32(sPipe);

    const int crow = tid >> 1;
    const int cch  = tid & 1;
    const uint32_t dstoff = (uint32_t)(crow * 48 + cch * 16);
    const __half* gP = d_PH + (size_t)(b0 + crow) * KC + cch * 8;
    const __half* gR = d_Rf + (size_t)(r0 + crow) * KC + cch * 8;

    const uint32_t offA = (uint32_t)((wm * 64 + (lane & 15)) * 48 + (lane >> 4) * 16);
    const uint32_t offB = (uint32_t)((wn * 32 + (lane & 7) + ((lane >> 4) & 1) * 8) * 48
                                     + ((lane >> 3) & 1) * 16) + 6144;

    float d[4][4][4];
#pragma unroll
    for (int i = 0; i < 4; i++)
#pragma unroll
        for (int j = 0; j < 4; j++)
#pragma unroll
            for (int k = 0; k < 4; k++) d[i][j][k] = 0.f;

#pragma unroll
    for (int s = 0; s < 2; s++) {
        uint32_t sb = base_u + s * STG3;
        cpasync16(sb + dstoff, gP + s * 16);
        cpasync16(sb + 6144 + dstoff, gR + s * 16);
        cpcommit();
    }

    uint32_t sOff = 0;
    for (int ks = 0; ks < NKS; ks++) {
        if (ks < NKS - 1) cpwait1(); else cpwait0();
        __syncthreads();

        if (ks + 2 < NKS) {
            uint32_t pOff = sOff + 2 * STG3; if (pOff >= 3 * STG3) pOff -= 3 * STG3;
            uint32_t sb = base_u + pOff;
            int koff = (ks + 2) * 16;
            cpasync16(sb + dstoff, gP + koff);
            cpasync16(sb + 6144 + dstoff, gR + koff);
            cpcommit();
        }

        uint32_t sb = base_u + sOff;
        uint32_t bb[2][4];
        ldsm4(bb[0], sb + offB);
        ldsm4(bb[1], sb + offB + 768);
#pragma unroll
        for (int mi = 0; mi < 4; mi++) {
            uint32_t a[4];
            ldsm4(a, sb + offA + mi * 768);
            mma16816(d[mi][0], a, bb[0]);
            mma16816(d[mi][1], a, bb[0] + 2);
            mma16816(d[mi][2], a, bb[1]);
            mma16816(d[mi][3], a, bb[1] + 2);
        }
        sOff += STG3; if (sOff == 3 * STG3) sOff = 0;
    }

    int mbase = b0 + wm * 64 + (lane >> 2);
    int nbase = r0 + wn * 32 + (lane & 3) * 2;
#pragma unroll
    for (int mi = 0; mi < 4; mi++) {
        int m = mbase + mi * 16;
#pragma unroll
        for (int t = 0; t < 4; t++) {
            int n = nbase + t * 8;
            if (n < R3) {
                size_t o1 = (size_t)m * R3 + n;
                size_t o2 = (size_t)(m + 8) * R3 + n;
                float2 v01 = make_float2(d[mi][t][0], d[mi][t][1]);
                float2 v23 = make_float2(d[mi][t][2], d[mi][t][3]);
                *(float2*)(out_vposed + o1) = v01;
                *(float2*)(out_naked  + o1) = v01;
                *(float2*)(out_vposed + o2) = v23;
                *(float2*)(out_naked  + o2) = v23;
            }
        }
    }
}

// ---------------------------------------------------------------------------
// skin via mma.sync fp16: T = W @ A2 fused with apply. (R15-proven, 3 blk/SM)
// ---------------------------------------------------------------------------
__global__ __launch_bounds__(256, 3) void skin_mma_kernel(const float* __restrict__ trans,
                                                          const float* __restrict__ naked_in,
                                                          float* __restrict__ out_verts) {
    __shared__ __align__(16) __half sA[128 * 72];   // weights tile
    __shared__ __align__(16) __half sB[128 * 72];   // BA2 tile
    __shared__ __align__(8)  float  sH[8 * 386];    // naked slice
    float* sOut = (float*)sA;                       // overlay after mainloop

    const int tid  = threadIdx.x;
    const int wid  = tid >> 5;
    const int lane = tid & 31;
    const int wm = wid & 1;
    const int wn = wid >> 1;
    const int v0 = blockIdx.x * 128;
    const int b0 = blockIdx.y * 8;
    const int c0 = blockIdx.y * 128;

    for (int i = tid; i < 1024; i += 256) {
        int row = i >> 3, ch = i & 7;
        *(uint4*)&sA[row * 72 + ch * 8] = *(const uint4*)&d_Wf[(size_t)(v0 + row) * KW + ch * 8];
        *(uint4*)&sB[row * 72 + ch * 8] = *(const uint4*)&d_BA2[(size_t)(c0 + row) * KW + ch * 8];
    }
    for (int idx = tid; idx < 1536; idx += 256) {
        int b = idx / 192, off = (idx % 192) * 2;
        int gcol = v0 * 3 + off;
        float2 val = make_float2(0.f, 0.f);
        if (gcol < R3)
            val = *(const float2*)(naked_in + (size_t)(b0 + b) * R3 + gcol);
        sH[b * 386 + off]     = val.x;
        sH[b * 386 + off + 1] = val.y;
    }
    __syncthreads();

    const uint32_t offA = (uint32_t)((wm * 64 + (lane & 15)) * 144 + (lane >> 4) * 16);
    const uint32_t offB = (uint32_t)((wn * 32 + (lane & 7) + ((lane >> 4) & 1) * 8) * 144
                                     + ((lane >> 3) & 1) * 16);
    uint32_t aB = smem_u32(sA) + offA;
    uint32_t bB = smem_u32(sB) + offB;

    float d[4][4][4];
#pragma unroll
    for (int i = 0; i < 4; i++)
#pragma unroll
        for (int j = 0; j < 4; j++)
#pragma unroll
            for (int k = 0; k < 4; k++) d[i][j][k] = 0.f;

#pragma unroll
    for (int ks = 0; ks < 4; ks++) {
        uint32_t ko = ks * 32;
        uint32_t bb[2][4];
        ldsm4(bb[0], bB + ko);
        ldsm4(bb[1], bB + ko + 2304);
#pragma unroll
        for (int mi = 0; mi < 4; mi++) {
            uint32_t a[4];
            ldsm4(a, aB + ko + mi * 2304);
            mma16816(d[mi][0], a, bb[0]);
            mma16816(d[mi][1], a, bb[0] + 2);
            mma16816(d[mi][2], a, bb[1]);
            mma16816(d[mi][3], a, bb[1] + 2);
        }
    }
    __syncthreads();

    const int q = lane & 3;
#pragma unroll
    for (int u = 0; u < 2; u++) {
        int bl = wn * 2 + u;
        int bg = b0 + bl;
        float tx = trans[bg * 3 + 0], ty = trans[bg * 3 + 1], tz = trans[bg * 3 + 2];
#pragma unroll
        for (int mi = 0; mi < 4; mi++) {
#pragma unroll
            for (int rh = 0; rh < 2; rh++) {
                int vl = wm * 64 + mi * 16 + (lane >> 2) + rh * 8;
                int v = v0 + vl;
                bool valid = (v < NV);
                const float* hp = &sH[bl * 386 + vl * 3];
                float s0, s1;
                if ((q & 1) == 0) { s0 = hp[0]; s1 = hp[1]; }
                else              { s0 = hp[2]; s1 = 1.f; }
                float pA = d[mi][2 * u][rh * 2 + 0] * s0 + d[mi][2 * u][rh * 2 + 1] * s1;
                float pB = d[mi][2 * u + 1][rh * 2 + 0] * s0 + d[mi][2 * u + 1][rh * 2 + 1] * s1;
                pA += __shfl_xor_sync(0xffffffffu, pA, 1);
                pB += __shfl_xor_sync(0xffffffffu, pB, 1);
                if (valid) {
                    if (q == 0) {
                        sOut[bl * 386 + vl * 3 + 0] = pA + tx;
                        sOut[bl * 386 + vl * 3 + 2] = pB + tz;
                    } else if (q == 2) {
                        sOut[bl * 386 + vl * 3 + 1] = pA + ty;
                    }
                }
            }
        }
    }
    __syncthreads();

    for (int idx = tid; idx < 1536; idx += 256) {
        int b = idx / 192, off = (idx % 192) * 2;
        int gcol = v0 * 3 + off;
        if (gcol < R3) {
            float2 val = make_float2(sOut[b * 386 + off], sOut[b * 386 + off + 1]);
            *(float2*)(out_verts + (size_t)(b0 + b) * R3 + gcol) = val;
        }
    }
}

// ---------------------------------------------------------------------------
extern "C" void kernel_launch(void* const* d_in, const int* in_sizes, int n_in,
                              void* d_out, int out_size) {
    (void)in_sizes; (void)n_in; (void)out_size;
    const float* pose  = (const float*)d_in[0];
    const float* betas = (const float*)d_in[1];
    const float* trans = (const float*)d_in[2];
    const float* vt    = (const float*)d_in[3];
    const float* sd    = (const float*)d_in[4];
    const float* pd    = (const float*)d_in[5];
    const float* Jreg  = (const float*)d_in[6];
    const float* wgt   = (const float*)d_in[7];

    float* out        = (float*)d_out;
    float* out_verts  = out;
    float* out_jtr    = out_verts + (size_t)BATCH * R3;
    float* out_vposed = out_jtr   + (size_t)BATCH * NJ * 3;
    float* out_naked  = out_vposed + (size_t)BATCH * R3;

    int convThreads = MROWS * 62;
    convertR_kernel<<<(convThreads + 255) / 256, 256>>>(pd, sd, vt);              // 0
    jregP_kernel<<<dim3(NJ, JS), 256>>>(Jreg, vt, sd);                            // 1
    pose_kernel<<<BATCH, 128>>>(pose, betas, trans, out_jtr);                     // 2
    mma_naked_kernel<<<dim3(162, 4), 256>>>(out_vposed, out_naked);               // 3 (profiled)
    convertW_kernel<<<(NVP * 8 + 255) / 256, 256>>>(wgt);                         // 4
    skin_mma_kernel<<<dim3(NVP / 128, BATCH / 8), 256>>>(trans, out_naked, out_verts); // 5
}